// round 2
// baseline (speedup 1.0000x reference)
#include <cuda_runtime.h>
#include <cuda_bf16.h>

#define NN 100000
#define NE 3200000
#define DIN 128
#define DHID 64
#define DOUT 40

// Scratch (static __device__ arrays — no allocation). 16B-aligned for float4 ops.
__device__ __align__(16) float g_h1[NN * DHID];      // x@W1
__device__ __align__(16) float g_h1agg[NN * DHID];   // spmm1 out
__device__ __align__(16) float g_h2[NN * DOUT];      // relu(h1agg)@W2
__device__ __align__(16) float g_h2agg[NN * DOUT];   // spmm2 out
__device__ int g_dst[NE];
__device__ int g_src[NE];
__device__ int g_is_i32;   // 1 if edge_index buffer is int32, 0 if int64

// ---------------------------------------------------------------------------
// -1) dtype detection: sample first 256 int64-interpreted values.
//     True int64 data (values in [0,NN)): all pass -> flag 0.
//     int32 data read as int64: value = lo + hi*2^32 with hi a random node id
//     (nonzero w.p. ~1-1e-5) -> out of range -> flag 1. Deterministic.
// ---------------------------------------------------------------------------
__global__ void detect_dtype(const long long* __restrict__ ei) {
    __shared__ int bad;
    if (threadIdx.x == 0) bad = 0;
    __syncthreads();
    long long v = ei[threadIdx.x];          // reads first 2KB — safe either way
    if (v < 0 || v >= NN) atomicOr(&bad, 1);
    __syncthreads();
    if (threadIdx.x == 0) g_is_i32 = bad;
}

// ---------------------------------------------------------------------------
// 0) edge index conversion (branch on detected dtype), clamped for safety
// ---------------------------------------------------------------------------
__global__ void convert_edges(const void* __restrict__ eiv) {
    int i = blockIdx.x * blockDim.x + threadIdx.x;   // grid covers NE exactly
    int d, s;
    if (g_is_i32) {
        const int* e = (const int*)eiv;
        d = e[i];
        s = e[NE + i];
    } else {
        const long long* e = (const long long*)eiv;
        d = (int)e[i];
        s = (int)e[NE + i];
    }
    g_dst[i] = min(max(d, 0), NN - 1);
    g_src[i] = min(max(s, 0), NN - 1);
}

// ---------------------------------------------------------------------------
// 1) zero the two aggregation buffers
// ---------------------------------------------------------------------------
__global__ void zero_aggs() {
    const int n1 = NN * DHID / 4;   // 1,600,000
    const int n2 = NN * DOUT / 4;   // 1,000,000
    float4 z = make_float4(0.f, 0.f, 0.f, 0.f);
    float4* a1 = (float4*)g_h1agg;
    float4* a2 = (float4*)g_h2agg;
    for (int i = blockIdx.x * blockDim.x + threadIdx.x; i < n1; i += gridDim.x * blockDim.x)
        a1[i] = z;
    for (int i = blockIdx.x * blockDim.x + threadIdx.x; i < n2; i += gridDim.x * blockDim.x)
        a2[i] = z;
}

// ---------------------------------------------------------------------------
// 2) GEMM1: h1 = x[NN,128] @ W1[128,64]
//    Block tile: 32 rows x 64 cols, 256 threads, thread tile 2x4.
// ---------------------------------------------------------------------------
__global__ void gemm1(const float* __restrict__ x, const float* __restrict__ W1) {
    __shared__ float Xs[32][DIN];   // 16 KB
    __shared__ float Ws[DIN][DHID]; // 32 KB

    const int tid  = threadIdx.x;
    const int row0 = blockIdx.x * 32;

    const float4* W4  = (const float4*)W1;
    float4*       Ws4 = (float4*)Ws;
    #pragma unroll
    for (int i = 0; i < 8; i++) Ws4[tid + 256 * i] = W4[tid + 256 * i];

    const float4* X4  = (const float4*)x;
    float4*       Xs4 = (float4*)Xs;
    #pragma unroll
    for (int i = 0; i < 4; i++) {
        int idx = tid + 256 * i;
        Xs4[idx] = X4[(size_t)(row0 + (idx >> 5)) * 32 + (idx & 31)];
    }
    __syncthreads();

    const int ty = tid >> 4;   // 0..15 -> rows ty*2, ty*2+1
    const int tx = tid & 15;   // 0..15 -> cols tx*4..tx*4+3

    float4 acc0 = make_float4(0.f, 0.f, 0.f, 0.f);
    float4 acc1 = make_float4(0.f, 0.f, 0.f, 0.f);

    #pragma unroll 8
    for (int k = 0; k < DIN; k++) {
        float x0 = Xs[ty * 2 + 0][k];
        float x1 = Xs[ty * 2 + 1][k];
        float4 w = *(const float4*)&Ws[k][tx * 4];
        acc0.x += x0 * w.x; acc0.y += x0 * w.y; acc0.z += x0 * w.z; acc0.w += x0 * w.w;
        acc1.x += x1 * w.x; acc1.y += x1 * w.y; acc1.z += x1 * w.z; acc1.w += x1 * w.w;
    }

    float4* out = (float4*)g_h1;
    out[(size_t)(row0 + ty * 2 + 0) * 16 + tx] = acc0;
    out[(size_t)(row0 + ty * 2 + 1) * 16 + tx] = acc1;
}

// ---------------------------------------------------------------------------
// 3) SpMM1: h1agg[dst] += w * h1[src], 16 float4 chunks per edge.
// ---------------------------------------------------------------------------
__global__ void spmm1(const float* __restrict__ ew) {
    int tid = blockIdx.x * 256 + threadIdx.x;
    int e = tid >> 4;
    int c = tid & 15;
    int src = g_src[e];
    int dst = g_dst[e];
    float w = ew[e];
    float4 v = ((const float4*)g_h1)[src * 16 + c];
    v.x *= w; v.y *= w; v.z *= w; v.w *= w;
    atomicAdd(((float4*)g_h1agg) + dst * 16 + c, v);
}

// ---------------------------------------------------------------------------
// 4) GEMM2: h2 = relu(h1agg)[NN,64] @ W2[64,40]
// ---------------------------------------------------------------------------
__global__ void gemm2(const float* __restrict__ W2) {
    __shared__ float Hs[64][DHID + 1];
    __shared__ float Ws[DHID * DOUT];

    const int tid  = threadIdx.x;
    const int row0 = blockIdx.x * 64;

    #pragma unroll
    for (int i = 0; i < 16; i++) {
        int idx = tid + 256 * i;
        int r = idx >> 6, c = idx & 63;
        float v = 0.f;
        if (row0 + r < NN) v = g_h1agg[(size_t)(row0 + r) * DHID + c];
        Hs[r][c] = fmaxf(v, 0.f);
    }
    #pragma unroll
    for (int i = 0; i < 10; i++) Ws[tid + 256 * i] = W2[tid + 256 * i];
    __syncthreads();

    const int ty = tid >> 3;  // 0..31 -> rows ty*2, ty*2+1
    const int tx = tid & 7;   // 0..7  -> cols tx*5..tx*5+4

    float acc[2][5] = {};
    #pragma unroll 8
    for (int k = 0; k < DHID; k++) {
        float h0  = Hs[ty * 2 + 0][k];
        float h1v = Hs[ty * 2 + 1][k];
        #pragma unroll
        for (int j = 0; j < 5; j++) {
            float w = Ws[k * DOUT + tx * 5 + j];
            acc[0][j] += h0 * w;
            acc[1][j] += h1v * w;
        }
    }

    #pragma unroll
    for (int i = 0; i < 2; i++) {
        int r = row0 + ty * 2 + i;
        if (r < NN) {
            #pragma unroll
            for (int j = 0; j < 5; j++)
                g_h2[(size_t)r * DOUT + tx * 5 + j] = acc[i][j];
        }
    }
}

// ---------------------------------------------------------------------------
// 5) SpMM2: h2agg[dst] += w * h2[src], 10 float4 chunks per edge.
//    blockDim=320: 32 edges per block. Grid NE/32 = 100000, exact.
// ---------------------------------------------------------------------------
__global__ void spmm2(const float* __restrict__ ew) {
    int le = threadIdx.x / 10;
    int c  = threadIdx.x % 10;
    int e  = blockIdx.x * 32 + le;
    int src = g_src[e];
    int dst = g_dst[e];
    float w = ew[e];
    float4 v = ((const float4*)g_h2)[src * 10 + c];
    v.x *= w; v.y *= w; v.z *= w; v.w *= w;
    atomicAdd(((float4*)g_h2agg) + dst * 10 + c, v);
}

// ---------------------------------------------------------------------------
// 6) log_softmax over 40 cols; one warp per row. Grid NN/8 = 12500, exact.
// ---------------------------------------------------------------------------
__global__ void logsoftmax(float* __restrict__ out) {
    int row  = blockIdx.x * 8 + (threadIdx.x >> 5);
    int lane = threadIdx.x & 31;
    const float* in = g_h2agg + (size_t)row * DOUT;

    float v0 = in[lane];
    float v1 = (lane < 8) ? in[32 + lane] : -3.402823466e+38f;

    float m = fmaxf(v0, v1);
    #pragma unroll
    for (int off = 16; off; off >>= 1) m = fmaxf(m, __shfl_xor_sync(0xffffffffu, m, off));

    float s = __expf(v0 - m) + ((lane < 8) ? __expf(v1 - m) : 0.f);
    #pragma unroll
    for (int off = 16; off; off >>= 1) s += __shfl_xor_sync(0xffffffffu, s, off);

    float lse = m + logf(s);
    float* o = out + (size_t)row * DOUT;
    o[lane] = v0 - lse;
    if (lane < 8) o[32 + lane] = v1 - lse;
}

// ---------------------------------------------------------------------------
extern "C" void kernel_launch(void* const* d_in, const int* in_sizes, int n_in,
                              void* d_out, int out_size) {
    const float* x  = (const float*)d_in[0];
    const void*  ei = d_in[1];
    const float* ew = (const float*)d_in[2];
    const float* W1 = (const float*)d_in[3];
    const float* W2 = (const float*)d_in[4];
    float* out = (float*)d_out;

    detect_dtype<<<1, 256>>>((const long long*)ei);
    convert_edges<<<NE / 256, 256>>>(ei);
    zero_aggs<<<2048, 256>>>();
    gemm1<<<NN / 32, 256>>>(x, W1);
    spmm1<<<(NE * 16) / 256, 256>>>(ew);
    gemm2<<<(NN + 63) / 64, 256>>>(W2);
    spmm2<<<NE / 32, 320>>>(ew);
    logsoftmax<<<NN / 8, 256>>>(out);
}